// round 11
// baseline (speedup 1.0000x reference)
#include <cuda_runtime.h>

// PlaneEmbeddingNetwork, R11: qkv precompute + fused attention kernel.
// K1: per-node qkv (+bias) -> g_qkv[node][head][32f] (row = half of a 256B
//     record; q8,k8,v8 packed in the first 24 floats, 128B-line contained).
// K2: per-(face,head) lanes, quads = 2 faces x 2 heads. Quad-cooperative
//     staged gather of the 16 qkv rows (1 line per quad per LDG.128),
//     conflict-free smem stage (R=20, Q=336 floats), then scores/softmax/
//     o=attn@v, progressive col-split W2, thread-local pool, butterfly,
//     quad-split fco. Removes ~1050 issue slots/thread vs R9.

typedef unsigned long long u64;

__device__ __forceinline__ u64 fma2(u64 a, u64 b, u64 c) {
    u64 d;
    asm("fma.rn.f32x2 %0, %1, %2, %3;" : "=l"(d) : "l"(a), "l"(b), "l"(c));
    return d;
}
__device__ __forceinline__ u64 pack2(float x, float y) {
    u64 r;
    asm("mov.b64 %0, {%1, %2};" : "=l"(r) : "f"(x), "f"(y));
    return r;
}
__device__ __forceinline__ float2 unpack2(u64 v) {
    float2 f;
    asm("mov.b64 {%0, %1}, %2;" : "=f"(f.x), "=f"(f.y) : "l"(v));
    return f;
}
__device__ __forceinline__ float getc(float4 v, int c) {
    return c == 0 ? v.x : (c == 1 ? v.y : (c == 2 ? v.z : v.w));
}

// Static scratch (allocation-free rule).
__device__ __align__(256) float g_qkv[250000 * 64];   // [node][h][32f], 24 used
__device__ float g_W2[16 * 32];                       // fused w_out @ fc_w
__device__ float g_b2[32];                            // fc_b + b_out @ fc_w

// ---------------------------------------------------------------------------
__global__ void prep_kernel(const float* __restrict__ w_out, const float* __restrict__ b_out,
                            const float* __restrict__ fc_w, const float* __restrict__ fc_b) {
    int i = threadIdx.x;
    if (i < 512) {
        int d = i >> 5, j = i & 31;
        float s = 0.f;
#pragma unroll
        for (int e = 0; e < 16; e++) s += w_out[d * 16 + e] * fc_w[e * 32 + j];
        g_W2[i] = s;
    }
    if (i < 32) {
        float s = fc_b[i];
#pragma unroll
        for (int e = 0; e < 16; e++) s += b_out[e] * fc_w[e * 32 + i];
        g_b2[i] = s;
    }
}

// ---------------------------------------------------------------------------
// K1: thread = (node-pair, head). qkv+bias (own head, 24 cols) for 2 nodes.
__global__ void __launch_bounds__(128)
qkv_kernel(const float* __restrict__ node, const float* __restrict__ w_in,
           const float* __restrict__ b_in, int Nn) {
    __shared__ __align__(16) float s_w[768];
    __shared__ __align__(16) float s_b[48];
    int tid = threadIdx.x;
    for (int i = tid; i < 768; i += 128) s_w[i] = w_in[i];
    if (tid < 48) s_b[tid] = b_in[tid];
    __syncthreads();

    int gi = blockIdx.x * 128 + tid;
    int h = gi & 1;
    int g = gi >> 1;
    int npairs = Nn >> 1;
    bool valid = g < npairs;
    if (!valid) g = npairs - 1;
    int n0 = 2 * g, n1 = 2 * g + 1;

    float4 X0[4], X1[4];
    {
        const float4* r0 = (const float4*)(node + 16ll * n0);
        const float4* r1 = (const float4*)(node + 16ll * n1);
        X0[0] = r0[0]; X0[1] = r0[1]; X0[2] = r0[2]; X0[3] = r0[3];
        X1[0] = r1[0]; X1[1] = r1[1]; X1[2] = r1[2]; X1[3] = r1[3];
    }

    u64 a0[12], a1[12];   // [q0..3, k0..3, v0..3]
    {
        const u64* bq = (const u64*)(s_b + 8 * h);
        const u64* bk = (const u64*)(s_b + 16 + 8 * h);
        const u64* bv = (const u64*)(s_b + 32 + 8 * h);
#pragma unroll
        for (int j = 0; j < 4; j++) {
            a0[j] = bq[j];     a1[j] = bq[j];
            a0[4 + j] = bk[j]; a1[4 + j] = bk[j];
            a0[8 + j] = bv[j]; a1[8 + j] = bv[j];
        }
    }
#pragma unroll
    for (int d = 0; d < 16; d++) {
        const float* w = s_w + d * 48 + 8 * h;
        ulonglong2 wqa = *(const ulonglong2*)(w);
        ulonglong2 wqb = *(const ulonglong2*)(w + 4);
        ulonglong2 wka = *(const ulonglong2*)(w + 16);
        ulonglong2 wkb = *(const ulonglong2*)(w + 20);
        ulonglong2 wva = *(const ulonglong2*)(w + 32);
        ulonglong2 wvb = *(const ulonglong2*)(w + 36);
        float x0 = getc(X0[d >> 2], d & 3);
        float x1 = getc(X1[d >> 2], d & 3);
        u64 p0 = pack2(x0, x0), p1 = pack2(x1, x1);
        a0[0] = fma2(p0, wqa.x, a0[0]);  a0[1] = fma2(p0, wqa.y, a0[1]);
        a0[2] = fma2(p0, wqb.x, a0[2]);  a0[3] = fma2(p0, wqb.y, a0[3]);
        a0[4] = fma2(p0, wka.x, a0[4]);  a0[5] = fma2(p0, wka.y, a0[5]);
        a0[6] = fma2(p0, wkb.x, a0[6]);  a0[7] = fma2(p0, wkb.y, a0[7]);
        a0[8] = fma2(p0, wva.x, a0[8]);  a0[9] = fma2(p0, wva.y, a0[9]);
        a0[10] = fma2(p0, wvb.x, a0[10]); a0[11] = fma2(p0, wvb.y, a0[11]);
        a1[0] = fma2(p1, wqa.x, a1[0]);  a1[1] = fma2(p1, wqa.y, a1[1]);
        a1[2] = fma2(p1, wqb.x, a1[2]);  a1[3] = fma2(p1, wqb.y, a1[3]);
        a1[4] = fma2(p1, wka.x, a1[4]);  a1[5] = fma2(p1, wka.y, a1[5]);
        a1[6] = fma2(p1, wkb.x, a1[6]);  a1[7] = fma2(p1, wkb.y, a1[7]);
        a1[8] = fma2(p1, wva.x, a1[8]);  a1[9] = fma2(p1, wva.y, a1[9]);
        a1[10] = fma2(p1, wvb.x, a1[10]); a1[11] = fma2(p1, wvb.y, a1[11]);
    }

    if (valid) {
        float* o0 = g_qkv + (size_t)n0 * 64 + h * 32;
        float* o1 = g_qkv + (size_t)n1 * 64 + h * 32;
#pragma unroll
        for (int j = 0; j < 6; j++) {
            float2 x = unpack2(a0[2 * j]), y = unpack2(a0[2 * j + 1]);
            ((float4*)o0)[j] = make_float4(x.x, x.y, y.x, y.y);
        }
#pragma unroll
        for (int j = 0; j < 6; j++) {
            float2 x = unpack2(a1[2 * j]), y = unpack2(a1[2 * j + 1]);
            ((float4*)o1)[j] = make_float4(x.x, x.y, y.x, y.y);
        }
    }
}

// ---------------------------------------------------------------------------
// K2: attention + W2 + pool + fco. Dynamic smem:
//   stage: 4 warps x 8 quads x 336 floats (16 rows of 20f per quad)
//   then W2(512), b2(32), fco(1024), fcob(32).
#define STAGE_R 20
#define STAGE_Q 336
#define STAGE_WARP (8 * STAGE_Q)          // 2688
#define SMEM_FLOATS (4 * STAGE_WARP + 512 + 32 + 1024 + 32)   // 12352

__global__ void __launch_bounds__(128, 4)
face_kernel(const int* __restrict__ fids,
            const float* __restrict__ fco_w, const float* __restrict__ fco_b,
            float* __restrict__ out, int F) {
    extern __shared__ __align__(16) float smem[];
    float* s_W2   = smem + 4 * STAGE_WARP;
    float* s_b2   = s_W2 + 512;
    float* s_fco  = s_b2 + 32;
    float* s_fcob = s_fco + 1024;

    int tid = threadIdx.x;
    for (int i = tid; i < 512; i += 128) s_W2[i] = g_W2[i];
    if (tid < 32) s_b2[tid] = g_b2[tid];
    for (int i = tid; i < 1024; i += 128) s_fco[i] = fco_w[i];
    if (tid < 32) s_fcob[tid] = fco_b[tid];
    __syncthreads();

    int gt = blockIdx.x * 128 + tid;
    int faceR = gt >> 1;            // real face (may be >= F for tail lanes)
    int h = gt & 1;                 // head index
    bool valid = faceR < F;
    int face = valid ? faceR : (F - 1);

    int lane = tid & 31;
    int wq = lane >> 2;             // quad in warp (0..7)
    int ql = lane & 3;              // role in quad: 2*faceSel + h

    // ---- face edge ids; both quad faces via shfl ----
    int4 Im = *(const int4*)(fids + 4ll * face);
    int ox = __shfl_xor_sync(0xffffffffu, Im.x, 2);
    int oy = __shfl_xor_sync(0xffffffffu, Im.y, 2);
    int oz = __shfl_xor_sync(0xffffffffu, Im.z, 2);
    int ow = __shfl_xor_sync(0xffffffffu, Im.w, 2);
    bool isB = (lane & 2) != 0;
    int Aids[4], Bids[4];
    Aids[0] = isB ? ox : Im.x; Aids[1] = isB ? oy : Im.y;
    Aids[2] = isB ? oz : Im.z; Aids[3] = isB ? ow : Im.w;
    Bids[0] = isB ? Im.x : ox; Bids[1] = isB ? Im.y : oy;
    Bids[2] = isB ? Im.z : oz; Bids[3] = isB ? Im.w : ow;

    float* st = smem + (tid >> 5) * STAGE_WARP + wq * STAGE_Q;

    // ---- staged gather, q+k (rows j = role + 4t; chunk ql of row j) ----
    // Each LDG.128: 4 lanes cover one 64B q,k block -> 1 line per quad.
#pragma unroll
    for (int j = 0; j < 16; j++) {
        int role = j & 3, t = j >> 2;
        int nd = (role & 2) ? Bids[t] : Aids[t];
        float4 v = *(const float4*)(g_qkv + (size_t)nd * 64 + (role & 1) * 32 + 4 * ql);
        *(float4*)(st + j * STAGE_R + 4 * ql) = v;
    }
    __syncwarp();

    // readback my rows (ql + 4t): q8, k8
    u64 q2[4][4], k2[4][4];
#pragma unroll
    for (int t = 0; t < 4; t++) {
        const float* rp = st + (ql + 4 * t) * STAGE_R;
        ulonglong2 a = *(const ulonglong2*)(rp);
        ulonglong2 b = *(const ulonglong2*)(rp + 4);
        ulonglong2 c = *(const ulonglong2*)(rp + 8);
        ulonglong2 d = *(const ulonglong2*)(rp + 12);
        q2[t][0] = a.x; q2[t][1] = a.y; q2[t][2] = b.x; q2[t][3] = b.y;
        k2[t][0] = c.x; k2[t][1] = c.y; k2[t][2] = d.x; k2[t][3] = d.y;
    }

    // ---- scores + softmax (own head, 4x4, global token order) ----
    float att[4][4];
    const float RS = 0.35355339059327373f;  // 1/sqrt(8)
#pragma unroll
    for (int qi = 0; qi < 4; qi++) {
#pragma unroll
        for (int ki = 0; ki < 4; ki++) {
            u64 a = fma2(q2[qi][0], k2[ki][0], 0ull);
            a = fma2(q2[qi][1], k2[ki][1], a);
            a = fma2(q2[qi][2], k2[ki][2], a);
            a = fma2(q2[qi][3], k2[ki][3], a);
            float2 p = unpack2(a);
            att[qi][ki] = (p.x + p.y) * RS;
        }
        float m = fmaxf(fmaxf(att[qi][0], att[qi][1]), fmaxf(att[qi][2], att[qi][3]));
        float e0 = __expf(att[qi][0] - m);
        float e1 = __expf(att[qi][1] - m);
        float e2 = __expf(att[qi][2] - m);
        float e3 = __expf(att[qi][3] - m);
        float inv = 1.0f / (e0 + e1 + e2 + e3);
        att[qi][0] = e0 * inv; att[qi][1] = e1 * inv;
        att[qi][2] = e2 * inv; att[qi][3] = e3 * inv;
    }

    // ---- staged gather, v (2 rows per instr, 2 lanes each) ----
    __syncwarp();   // all lanes done reading q,k before overwrite
#pragma unroll
    for (int i = 0; i < 8; i++) {
        int rv = 2 * i + (ql >> 1);
        int role = rv & 3, t = rv >> 2;
        int nd = (role & 2) ? Bids[t] : Aids[t];
        float4 v = *(const float4*)(g_qkv + (size_t)nd * 64 + (role & 1) * 32 + 16 + 4 * (ql & 1));
        *(float4*)(st + rv * STAGE_R + 4 * (ql & 1)) = v;
    }
    __syncwarp();
    u64 v2[4][4];
#pragma unroll
    for (int t = 0; t < 4; t++) {
        const float* rp = st + (ql + 4 * t) * STAGE_R;
        ulonglong2 a = *(const ulonglong2*)(rp);
        ulonglong2 b = *(const ulonglong2*)(rp + 4);
        v2[t][0] = a.x; v2[t][1] = a.y; v2[t][2] = b.x; v2[t][3] = b.y;
    }

    // ---- o = attn @ v (own head half: 8 dims, 4 query tokens) ----
    u64 o2[4][4];
#pragma unroll
    for (int qi = 0; qi < 4; qi++) {
#pragma unroll
        for (int j = 0; j < 4; j++) o2[qi][j] = 0ull;
#pragma unroll
        for (int s = 0; s < 4; s++) {
            u64 a2 = pack2(att[qi][s], att[qi][s]);
#pragma unroll
            for (int j = 0; j < 4; j++) o2[qi][j] = fma2(a2, v2[s][j], o2[qi][j]);
        }
    }

    // ---- W2 col-split (cols [16h,16h+16)) with progressive o-exchange ----
    u64 acc[4][8];
    {
        const u64* bb = (const u64*)(s_b2 + 16 * h);
#pragma unroll
        for (int t = 0; t < 4; t++)
#pragma unroll
            for (int j = 0; j < 8; j++) acc[t][j] = bb[j];
    }
    {
        const float* wbaseA = s_W2 + (8 * h) * 32 + 16 * h;
#pragma unroll
        for (int dd = 0; dd < 8; dd++) {
            const ulonglong2* wr = (const ulonglong2*)(wbaseA + dd * 32);
            ulonglong2 wa = wr[0], wb = wr[1], wc = wr[2], wd_ = wr[3];
#pragma unroll
            for (int t = 0; t < 4; t++) {
                float2 p = unpack2(o2[t][dd >> 1]);
                float ov = (dd & 1) ? p.y : p.x;
                u64 op = pack2(ov, ov);
                acc[t][0] = fma2(op, wa.x, acc[t][0]);
                acc[t][1] = fma2(op, wa.y, acc[t][1]);
                acc[t][2] = fma2(op, wb.x, acc[t][2]);
                acc[t][3] = fma2(op, wb.y, acc[t][3]);
                acc[t][4] = fma2(op, wc.x, acc[t][4]);
                acc[t][5] = fma2(op, wc.y, acc[t][5]);
                acc[t][6] = fma2(op, wd_.x, acc[t][6]);
                acc[t][7] = fma2(op, wd_.y, acc[t][7]);
            }
        }
    }
    // exchange: partner lane (^1) = other head, SAME face, same token order
    u64 rcv[4][4];
#pragma unroll
    for (int t = 0; t < 4; t++)
#pragma unroll
        for (int j = 0; j < 4; j++)
            rcv[t][j] = __shfl_xor_sync(0xffffffffu, o2[t][j], 1);
    {
        const float* wbaseB = s_W2 + (8 * (1 - h)) * 32 + 16 * h;
#pragma unroll
        for (int dd = 0; dd < 8; dd++) {
            const ulonglong2* wr = (const ulonglong2*)(wbaseB + dd * 32);
            ulonglong2 wa = wr[0], wb = wr[1], wc = wr[2], wd_ = wr[3];
#pragma unroll
            for (int t = 0; t < 4; t++) {
                float2 p = unpack2(rcv[t][dd >> 1]);
                float ov = (dd & 1) ? p.y : p.x;
                u64 op = pack2(ov, ov);
                acc[t][0] = fma2(op, wa.x, acc[t][0]);
                acc[t][1] = fma2(op, wa.y, acc[t][1]);
                acc[t][2] = fma2(op, wb.x, acc[t][2]);
                acc[t][3] = fma2(op, wb.y, acc[t][3]);
                acc[t][4] = fma2(op, wc.x, acc[t][4]);
                acc[t][5] = fma2(op, wc.y, acc[t][5]);
                acc[t][6] = fma2(op, wd_.x, acc[t][6]);
                acc[t][7] = fma2(op, wd_.y, acc[t][7]);
            }
        }
    }

    // ---- relu + mean over 4 tokens (thread-local) ----
    u64 pool[8];
#pragma unroll
    for (int j = 0; j < 8; j++) {
        float px = 0.f, py = 0.f;
#pragma unroll
        for (int t = 0; t < 4; t++) {
            float2 a = unpack2(acc[t][j]);
            px += fmaxf(a.x, 0.f);
            py += fmaxf(a.y, 0.f);
        }
        pool[j] = pack2(px * 0.25f, py * 0.25f);
    }

    // ---- butterfly: full 32 pooled own face (xor1), partner face (xor2) ----
    u64 pown[16];
#pragma unroll
    for (int j = 0; j < 8; j++) {
        u64 other = __shfl_xor_sync(0xffffffffu, pool[j], 1);
        pown[j]     = h ? other : pool[j];
        pown[8 + j] = h ? pool[j] : other;
    }
    u64 poth[16];
#pragma unroll
    for (int j = 0; j < 16; j++)
        poth[j] = __shfl_xor_sync(0xffffffffu, pown[j], 2);

    // ---- fco quad-split: col octet [8c,8c+8), c = tid&3, both quad faces ----
    int c = tid & 3;
    u64 accA[4], accB[4];
    {
        const u64* fb = (const u64*)(s_fcob + 8 * c);
#pragma unroll
        for (int p = 0; p < 4; p++) { accA[p] = fb[p]; accB[p] = fb[p]; }
    }
    const float* fch = s_fco + 8 * c;
#pragma unroll
    for (int e = 0; e < 32; e++) {
        float2 ppA = unpack2(pown[e >> 1]);
        float2 ppB = unpack2(poth[e >> 1]);
        float peA = (e & 1) ? ppA.y : ppA.x;
        float peB = (e & 1) ? ppB.y : ppB.x;
        u64 pA2 = pack2(peA, peA);
        u64 pB2 = pack2(peB, peB);
        const ulonglong2* fr = (const ulonglong2*)(fch + e * 32);
        ulonglong2 wa = fr[0], wb = fr[1];
        accA[0] = fma2(pA2, wa.x, accA[0]);
        accA[1] = fma2(pA2, wa.y, accA[1]);
        accA[2] = fma2(pA2, wb.x, accA[2]);
        accA[3] = fma2(pA2, wb.y, accA[3]);
        accB[0] = fma2(pB2, wa.x, accB[0]);
        accB[1] = fma2(pB2, wa.y, accB[1]);
        accB[2] = fma2(pB2, wb.x, accB[2]);
        accB[3] = fma2(pB2, wb.y, accB[3]);
    }

    int faceB = faceR ^ 1;
    if (valid) {
        float* opA = out + 32ll * faceR + 8 * c;
        float2 a0 = unpack2(accA[0]), a1 = unpack2(accA[1]);
        float2 a2 = unpack2(accA[2]), a3 = unpack2(accA[3]);
        ((float4*)opA)[0] = make_float4(a0.x, a0.y, a1.x, a1.y);
        ((float4*)opA)[1] = make_float4(a2.x, a2.y, a3.x, a3.y);
    }
    if (faceB < F) {
        float* opB = out + 32ll * faceB + 8 * c;
        float2 b0 = unpack2(accB[0]), b1 = unpack2(accB[1]);
        float2 b2 = unpack2(accB[2]), b3 = unpack2(accB[3]);
        ((float4*)opB)[0] = make_float4(b0.x, b0.y, b1.x, b1.y);
        ((float4*)opB)[1] = make_float4(b2.x, b2.y, b3.x, b3.y);
    }
}

// ---------------------------------------------------------------------------
extern "C" void kernel_launch(void* const* d_in, const int* in_sizes, int n_in,
                              void* d_out, int out_size) {
    const float* node  = (const float*)d_in[0];
    const int*   fids  = (const int*)d_in[1];
    const float* w_in  = (const float*)d_in[2];
    const float* b_in  = (const float*)d_in[3];
    const float* w_out = (const float*)d_in[4];
    const float* b_out = (const float*)d_in[5];
    const float* fc_w  = (const float*)d_in[6];
    const float* fc_b  = (const float*)d_in[7];
    const float* fco_w = (const float*)d_in[8];
    const float* fco_b = (const float*)d_in[9];

    int Nn = in_sizes[0] / 16;   // 250000
    int F  = in_sizes[1] / 4;    // 500000

    int smem_bytes = SMEM_FLOATS * 4;   // 49408
    cudaFuncSetAttribute(face_kernel, cudaFuncAttributeMaxDynamicSharedMemorySize,
                         smem_bytes);

    prep_kernel<<<1, 512>>>(w_out, b_out, fc_w, fc_b);
    qkv_kernel<<<(Nn + 127) / 128, 128>>>(node, w_in, b_in, Nn);

    long long threads = 2ll * F;
    int blocks = (int)((threads + 127) / 128);
    face_kernel<<<blocks, 128, smem_bytes>>>(fids, fco_w, fco_b, (float*)d_out, F);
}

// round 12
// speedup vs baseline: 1.3583x; 1.3583x over previous
#include <cuda_runtime.h>

// PlaneEmbeddingNetwork fused kernel for GB300 (sm_103a), R12.
// = R9 (best: 147.5us) + R10's progressive o-exchange W2 phase at the SAFE
// (128,4) launch bound (R10's regression was the (128,5) register clamp
// forcing rematerialization, not the progressive exchange itself).
// Quad-cooperative gather, lane-local token order, col-split W2, thread-local
// pool, butterfly, quad-split fco. All heavy math in packed fp32 FMA.

typedef unsigned long long u64;

__device__ __forceinline__ u64 fma2(u64 a, u64 b, u64 c) {
    u64 d;
    asm("fma.rn.f32x2 %0, %1, %2, %3;" : "=l"(d) : "l"(a), "l"(b), "l"(c));
    return d;
}
__device__ __forceinline__ u64 pack2(float x, float y) {
    u64 r;
    asm("mov.b64 %0, {%1, %2};" : "=l"(r) : "f"(x), "f"(y));
    return r;
}
__device__ __forceinline__ float2 unpack2(u64 v) {
    float2 f;
    asm("mov.b64 {%0, %1}, %2;" : "=f"(f.x), "=f"(f.y) : "l"(v));
    return f;
}
__device__ __forceinline__ float getc(float4 v, int c) {
    return c == 0 ? v.x : (c == 1 ? v.y : (c == 2 ? v.z : v.w));
}

// Fused weights computed once by prep kernel:
//   W2[d][j] = sum_e w_out[d][e] * fc_w[e][j]    (16 x 32)
//   b2[j]    = fc_b[j] + sum_e b_out[e] * fc_w[e][j]
__device__ float g_W2[16 * 32];
__device__ float g_b2[32];

__global__ void prep_kernel(const float* __restrict__ w_out, const float* __restrict__ b_out,
                            const float* __restrict__ fc_w, const float* __restrict__ fc_b) {
    int i = threadIdx.x;
    if (i < 512) {
        int d = i >> 5, j = i & 31;
        float s = 0.f;
#pragma unroll
        for (int e = 0; e < 16; e++) s += w_out[d * 16 + e] * fc_w[e * 32 + j];
        g_W2[i] = s;
    }
    if (i < 32) {
        float s = fc_b[i];
#pragma unroll
        for (int e = 0; e < 16; e++) s += b_out[e] * fc_w[e * 32 + i];
        g_b2[i] = s;
    }
}

__global__ void __launch_bounds__(128, 4)
face_kernel(const float* __restrict__ node, const int* __restrict__ fids,
            const float* __restrict__ w_in, const float* __restrict__ b_in,
            const float* __restrict__ fco_w, const float* __restrict__ fco_b,
            float* __restrict__ out, int F) {
    __shared__ __align__(16) float s_win[16 * 48];   // packed qkv weights [d][o]
    __shared__ __align__(16) float s_bin[48];
    __shared__ __align__(16) float s_W2[16 * 32];    // fused w_out@fc_w
    __shared__ __align__(16) float s_b2[32];
    __shared__ __align__(16) float s_fco[32 * 32];
    __shared__ __align__(16) float s_fcob[32];
    __shared__ __align__(16) float s_stage[4][8][132];  // [warp][slot][quad*16+chunk*4]

    int tid = threadIdx.x;
    for (int i = tid; i < 768; i += 128) s_win[i] = w_in[i];
    if (tid < 48) s_bin[tid] = b_in[tid];
    for (int i = tid; i < 512; i += 128) s_W2[i] = g_W2[i];
    if (tid < 32) s_b2[tid] = g_b2[tid];
    for (int i = tid; i < 1024; i += 128) s_fco[i] = fco_w[i];
    if (tid < 32) s_fcob[tid] = fco_b[tid];
    __syncthreads();

    int gt = blockIdx.x * 128 + tid;
    int faceR = gt >> 1;            // real face (may be >= F for tail lanes)
    int h = gt & 1;                 // head index (0 or 1)
    bool valid = faceR < F;
    int face = valid ? faceR : (F - 1);  // clamped for loads

    int lane = tid & 31;
    int wq = lane >> 2;             // quad index within warp (0..7)
    int ql = lane & 3;              // lane within quad

    // ---- quad-cooperative gather (one LDG.128 touches 8 lines, not 32) ----
    int4 Im = *(const int4*)(fids + 4ll * face);
    int ox = __shfl_xor_sync(0xffffffffu, Im.x, 2);
    int oy = __shfl_xor_sync(0xffffffffu, Im.y, 2);
    int oz = __shfl_xor_sync(0xffffffffu, Im.z, 2);
    int ow = __shfl_xor_sync(0xffffffffu, Im.w, 2);
    bool isB = (lane & 2) != 0;
    int IAx = isB ? ox : Im.x, IAy = isB ? oy : Im.y;
    int IAz = isB ? oz : Im.z, IAw = isB ? ow : Im.w;
    int IBx = isB ? Im.x : ox, IBy = isB ? Im.y : oy;
    int IBz = isB ? Im.z : oz, IBw = isB ? Im.w : ow;
    float* st = &s_stage[tid >> 5][0][0];
    {
        long long co = 4 * ql;      // chunk offset in floats
        float4 r0 = *(const float4*)(node + 16ll * IAx + co);
        float4 r1 = *(const float4*)(node + 16ll * IAz + co);
        float4 r2 = *(const float4*)(node + 16ll * IBx + co);
        float4 r3 = *(const float4*)(node + 16ll * IBz + co);
        float4 r4 = *(const float4*)(node + 16ll * IAy + co);
        float4 r5 = *(const float4*)(node + 16ll * IAw + co);
        float4 r6 = *(const float4*)(node + 16ll * IBy + co);
        float4 r7 = *(const float4*)(node + 16ll * IBw + co);
        int so = wq * 16 + ql * 4;
        *(float4*)(st + 0 * 132 + so) = r0;
        *(float4*)(st + 1 * 132 + so) = r1;
        *(float4*)(st + 2 * 132 + so) = r2;
        *(float4*)(st + 3 * 132 + so) = r3;
        *(float4*)(st + 4 * 132 + so) = r4;
        *(float4*)(st + 5 * 132 + so) = r5;
        *(float4*)(st + 6 * 132 + so) = r6;
        *(float4*)(st + 7 * 132 + so) = r7;
    }
    __syncwarp();
    float4 XA[4], XB[4];
    {
        const float* pa = st + ql * 132 + wq * 16;
        const float* pb = st + (ql + 4) * 132 + wq * 16;
#pragma unroll
        for (int cc = 0; cc < 4; cc++) {
            XA[cc] = *(const float4*)(pa + cc * 4);
            XB[cc] = *(const float4*)(pb + cc * 4);
        }
    }

    // Lane-local token order: 0 = own_a, 1 = own_b, 2 = partner_a, 3 = partner_b.

    // ---- phase 1a: q,k for all 4 tokens (own head), d-outer for weight reuse ----
    u64 q2[4][4], k2[4][4];
    {
        const u64* bq = (const u64*)(s_bin + 8 * h);
        const u64* bk = (const u64*)(s_bin + 16 + 8 * h);
#pragma unroll
        for (int t = 0; t < 4; t++)
#pragma unroll
            for (int j = 0; j < 4; j++) { q2[t][j] = bq[j]; k2[t][j] = bk[j]; }
    }
    {
        const float* wqp = s_win + 8 * h;
        const float* wkp = s_win + 16 + 8 * h;
#pragma unroll
        for (int d = 0; d < 16; d++) {
            ulonglong2 wq0 = *(const ulonglong2*)(wqp + d * 48);
            ulonglong2 wq1 = *(const ulonglong2*)(wqp + d * 48 + 4);
            ulonglong2 wk0 = *(const ulonglong2*)(wkp + d * 48);
            ulonglong2 wk1 = *(const ulonglong2*)(wkp + d * 48 + 4);
            float xa = getc(XA[d >> 2], d & 3);
            float xb = getc(XB[d >> 2], d & 3);
            float fa = __shfl_xor_sync(0xffffffffu, xa, 1);
            float fb = __shfl_xor_sync(0xffffffffu, xb, 1);
            u64 xt[4] = {pack2(xa, xa), pack2(xb, xb), pack2(fa, fa), pack2(fb, fb)};
#pragma unroll
            for (int t = 0; t < 4; t++) {
                q2[t][0] = fma2(xt[t], wq0.x, q2[t][0]);
                q2[t][1] = fma2(xt[t], wq0.y, q2[t][1]);
                q2[t][2] = fma2(xt[t], wq1.x, q2[t][2]);
                q2[t][3] = fma2(xt[t], wq1.y, q2[t][3]);
                k2[t][0] = fma2(xt[t], wk0.x, k2[t][0]);
                k2[t][1] = fma2(xt[t], wk0.y, k2[t][1]);
                k2[t][2] = fma2(xt[t], wk1.x, k2[t][2]);
                k2[t][3] = fma2(xt[t], wk1.y, k2[t][3]);
            }
        }
    }

    // ---- scores + softmax (own head, 4x4, lane-local token order) ----
    float att[4][4];
    const float RS = 0.35355339059327373f;  // 1/sqrt(8)
#pragma unroll
    for (int qi = 0; qi < 4; qi++) {
#pragma unroll
        for (int ki = 0; ki < 4; ki++) {
            u64 a = fma2(q2[qi][0], k2[ki][0], 0ull);
            a = fma2(q2[qi][1], k2[ki][1], a);
            a = fma2(q2[qi][2], k2[ki][2], a);
            a = fma2(q2[qi][3], k2[ki][3], a);
            float2 p = unpack2(a);
            att[qi][ki] = (p.x + p.y) * RS;
        }
        float m = fmaxf(fmaxf(att[qi][0], att[qi][1]), fmaxf(att[qi][2], att[qi][3]));
        float e0 = __expf(att[qi][0] - m);
        float e1 = __expf(att[qi][1] - m);
        float e2 = __expf(att[qi][2] - m);
        float e3 = __expf(att[qi][3] - m);
        float inv = 1.0f / (e0 + e1 + e2 + e3);
        att[qi][0] = e0 * inv; att[qi][1] = e1 * inv;
        att[qi][2] = e2 * inv; att[qi][3] = e3 * inv;
    }

    // ---- phase 1b: v for all 4 tokens (own head), d-outer ----
    u64 v2[4][4];
    {
        const u64* bv = (const u64*)(s_bin + 32 + 8 * h);
#pragma unroll
        for (int t = 0; t < 4; t++)
#pragma unroll
            for (int j = 0; j < 4; j++) v2[t][j] = bv[j];
    }
    {
        const float* wvp = s_win + 32 + 8 * h;
#pragma unroll
        for (int d = 0; d < 16; d++) {
            ulonglong2 wv0 = *(const ulonglong2*)(wvp + d * 48);
            ulonglong2 wv1 = *(const ulonglong2*)(wvp + d * 48 + 4);
            float xa = getc(XA[d >> 2], d & 3);
            float xb = getc(XB[d >> 2], d & 3);
            float fa = __shfl_xor_sync(0xffffffffu, xa, 1);
            float fb = __shfl_xor_sync(0xffffffffu, xb, 1);
            u64 xt[4] = {pack2(xa, xa), pack2(xb, xb), pack2(fa, fa), pack2(fb, fb)};
#pragma unroll
            for (int t = 0; t < 4; t++) {
                v2[t][0] = fma2(xt[t], wv0.x, v2[t][0]);
                v2[t][1] = fma2(xt[t], wv0.y, v2[t][1]);
                v2[t][2] = fma2(xt[t], wv1.x, v2[t][2]);
                v2[t][3] = fma2(xt[t], wv1.y, v2[t][3]);
            }
        }
    }

    // ---- o = attn @ v for all 4 local query tokens (own head half: 8 dims) ----
    u64 o2[4][4];
#pragma unroll
    for (int qi = 0; qi < 4; qi++) {
#pragma unroll
        for (int j = 0; j < 4; j++) o2[qi][j] = 0ull;
#pragma unroll
        for (int s = 0; s < 4; s++) {
            u64 a2 = pack2(att[qi][s], att[qi][s]);
#pragma unroll
            for (int j = 0; j < 4; j++) o2[qi][j] = fma2(a2, v2[s][j], o2[qi][j]);
        }
    }

    // ---- W2 col-split with PROGRESSIVE o-exchange ----
    // acc[t] = cols [16h,16h+16) of token t. Phase A: own-head W2 rows
    // [8h,8h+8) consume o2 directly. Then exchange (o2 dies). Phase B:
    // other-head rows consume rcv. Per-lane summation order differs; fp-safe.
    u64 acc[4][8];
    {
        const u64* bb = (const u64*)(s_b2 + 16 * h);
#pragma unroll
        for (int t = 0; t < 4; t++)
#pragma unroll
            for (int j = 0; j < 8; j++) acc[t][j] = bb[j];
    }
    {
        const float* wbaseA = s_W2 + (8 * h) * 32 + 16 * h;
#pragma unroll
        for (int dd = 0; dd < 8; dd++) {
            const ulonglong2* wr = (const ulonglong2*)(wbaseA + dd * 32);
            ulonglong2 wa = wr[0], wb = wr[1], wc = wr[2], wd_ = wr[3];
#pragma unroll
            for (int t = 0; t < 4; t++) {
                float2 p = unpack2(o2[t][dd >> 1]);
                float ov = (dd & 1) ? p.y : p.x;
                u64 op = pack2(ov, ov);
                acc[t][0] = fma2(op, wa.x, acc[t][0]);
                acc[t][1] = fma2(op, wa.y, acc[t][1]);
                acc[t][2] = fma2(op, wb.x, acc[t][2]);
                acc[t][3] = fma2(op, wb.y, acc[t][3]);
                acc[t][4] = fma2(op, wc.x, acc[t][4]);
                acc[t][5] = fma2(op, wc.y, acc[t][5]);
                acc[t][6] = fma2(op, wd_.x, acc[t][6]);
                acc[t][7] = fma2(op, wd_.y, acc[t][7]);
            }
        }
    }
    // exchange: rcv[t] = partner's own-head o for my token t (their local t^2)
    u64 rcv[4][4];
#pragma unroll
    for (int t = 0; t < 4; t++)
#pragma unroll
        for (int j = 0; j < 4; j++)
            rcv[t][j] = __shfl_xor_sync(0xffffffffu, o2[t ^ 2][j], 1);
    {
        const float* wbaseB = s_W2 + (8 * (1 - h)) * 32 + 16 * h;
#pragma unroll
        for (int dd = 0; dd < 8; dd++) {
            const ulonglong2* wr = (const ulonglong2*)(wbaseB + dd * 32);
            ulonglong2 wa = wr[0], wb = wr[1], wc = wr[2], wd_ = wr[3];
#pragma unroll
            for (int t = 0; t < 4; t++) {
                float2 p = unpack2(rcv[t][dd >> 1]);
                float ov = (dd & 1) ? p.y : p.x;
                u64 op = pack2(ov, ov);
                acc[t][0] = fma2(op, wa.x, acc[t][0]);
                acc[t][1] = fma2(op, wa.y, acc[t][1]);
                acc[t][2] = fma2(op, wb.x, acc[t][2]);
                acc[t][3] = fma2(op, wb.y, acc[t][3]);
                acc[t][4] = fma2(op, wc.x, acc[t][4]);
                acc[t][5] = fma2(op, wc.y, acc[t][5]);
                acc[t][6] = fma2(op, wd_.x, acc[t][6]);
                acc[t][7] = fma2(op, wd_.y, acc[t][7]);
            }
        }
    }

    // ---- relu + mean over 4 tokens (thread-local) ----
    u64 pool[8];   // my 16 cols
#pragma unroll
    for (int j = 0; j < 8; j++) {
        float px = 0.f, py = 0.f;
#pragma unroll
        for (int t = 0; t < 4; t++) {
            float2 a = unpack2(acc[t][j]);
            px += fmaxf(a.x, 0.f);
            py += fmaxf(a.y, 0.f);
        }
        pool[j] = pack2(px * 0.25f, py * 0.25f);
    }

    // ---- butterfly: full 32 pooled for own face (xor1), then partner face (xor2) ----
    u64 pown[16];
#pragma unroll
    for (int j = 0; j < 8; j++) {
        u64 other = __shfl_xor_sync(0xffffffffu, pool[j], 1);
        pown[j]     = h ? other : pool[j];
        pown[8 + j] = h ? pool[j] : other;
    }
    u64 poth[16];
#pragma unroll
    for (int j = 0; j < 16; j++)
        poth[j] = __shfl_xor_sync(0xffffffffu, pown[j], 2);

    // ---- fco quad-split: col octet [8c, 8c+8), c = tid&3, for BOTH quad faces ----
    int c = tid & 3;
    u64 accA[4], accB[4];
    {
        const u64* fb = (const u64*)(s_fcob + 8 * c);
#pragma unroll
        for (int p = 0; p < 4; p++) { accA[p] = fb[p]; accB[p] = fb[p]; }
    }
    const float* fch = s_fco + 8 * c;
#pragma unroll
    for (int e = 0; e < 32; e++) {
        float2 ppA = unpack2(pown[e >> 1]);
        float2 ppB = unpack2(poth[e >> 1]);
        float peA = (e & 1) ? ppA.y : ppA.x;
        float peB = (e & 1) ? ppB.y : ppB.x;
        u64 pA2 = pack2(peA, peA);
        u64 pB2 = pack2(peB, peB);
        const ulonglong2* fr = (const ulonglong2*)(fch + e * 32);
        ulonglong2 wa = fr[0], wb = fr[1];
        accA[0] = fma2(pA2, wa.x, accA[0]);
        accA[1] = fma2(pA2, wa.y, accA[1]);
        accA[2] = fma2(pA2, wb.x, accA[2]);
        accA[3] = fma2(pA2, wb.y, accA[3]);
        accB[0] = fma2(pB2, wa.x, accB[0]);
        accB[1] = fma2(pB2, wa.y, accB[1]);
        accB[2] = fma2(pB2, wb.x, accB[2]);
        accB[3] = fma2(pB2, wb.y, accB[3]);
    }

    // ---- stores: face A = my real face; face B = quad partner's face (^1) ----
    int faceB = faceR ^ 1;
    if (valid) {
        float* opA = out + 32ll * faceR + 8 * c;
        float2 a0 = unpack2(accA[0]), a1 = unpack2(accA[1]);
        float2 a2 = unpack2(accA[2]), a3 = unpack2(accA[3]);
        ((float4*)opA)[0] = make_float4(a0.x, a0.y, a1.x, a1.y);
        ((float4*)opA)[1] = make_float4(a2.x, a2.y, a3.x, a3.y);
    }
    if (faceB < F) {
        float* opB = out + 32ll * faceB + 8 * c;
        float2 b0 = unpack2(accB[0]), b1 = unpack2(accB[1]);
        float2 b2 = unpack2(accB[2]), b3 = unpack2(accB[3]);
        ((float4*)opB)[0] = make_float4(b0.x, b0.y, b1.x, b1.y);
        ((float4*)opB)[1] = make_float4(b2.x, b2.y, b3.x, b3.y);
    }
}

extern "C" void kernel_launch(void* const* d_in, const int* in_sizes, int n_in,
                              void* d_out, int out_size) {
    const float* node  = (const float*)d_in[0];
    const int*   fids  = (const int*)d_in[1];
    const float* w_in  = (const float*)d_in[2];
    const float* b_in  = (const float*)d_in[3];
    const float* w_out = (const float*)d_in[4];
    const float* b_out = (const float*)d_in[5];
    const float* fc_w  = (const float*)d_in[6];
    const float* fc_b  = (const float*)d_in[7];
    const float* fco_w = (const float*)d_in[8];
    const float* fco_b = (const float*)d_in[9];

    int F = in_sizes[1] / 4;

    prep_kernel<<<1, 512>>>(w_out, b_out, fc_w, fc_b);

    long long threads = 2ll * F;
    int blocks = (int)((threads + 127) / 128);
    face_kernel<<<blocks, 128>>>(node, fids, w_in, b_in, fco_w, fco_b, (float*)d_out, F);
}

// round 13
// speedup vs baseline: 1.3823x; 1.0177x over previous
#include <cuda_runtime.h>

// PlaneEmbeddingNetwork fused kernel for GB300 (sm_103a), R13.
// = R12 (best: 143.9us) with the gather hoisted ahead of the weight smem
// fills: fids LDG + 8 node LDGs are issued first, the 12 weight-fill
// LDG->STS pairs overlap their latency, and __syncthreads is deferred to
// just before the first weight use. Math is bit-identical to R12.

typedef unsigned long long u64;

__device__ __forceinline__ u64 fma2(u64 a, u64 b, u64 c) {
    u64 d;
    asm("fma.rn.f32x2 %0, %1, %2, %3;" : "=l"(d) : "l"(a), "l"(b), "l"(c));
    return d;
}
__device__ __forceinline__ u64 pack2(float x, float y) {
    u64 r;
    asm("mov.b64 %0, {%1, %2};" : "=l"(r) : "f"(x), "f"(y));
    return r;
}
__device__ __forceinline__ float2 unpack2(u64 v) {
    float2 f;
    asm("mov.b64 {%0, %1}, %2;" : "=f"(f.x), "=f"(f.y) : "l"(v));
    return f;
}
__device__ __forceinline__ float getc(float4 v, int c) {
    return c == 0 ? v.x : (c == 1 ? v.y : (c == 2 ? v.z : v.w));
}

// Fused weights computed once by prep kernel:
//   W2[d][j] = sum_e w_out[d][e] * fc_w[e][j]    (16 x 32)
//   b2[j]    = fc_b[j] + sum_e b_out[e] * fc_w[e][j]
__device__ float g_W2[16 * 32];
__device__ float g_b2[32];

__global__ void prep_kernel(const float* __restrict__ w_out, const float* __restrict__ b_out,
                            const float* __restrict__ fc_w, const float* __restrict__ fc_b) {
    int i = threadIdx.x;
    if (i < 512) {
        int d = i >> 5, j = i & 31;
        float s = 0.f;
#pragma unroll
        for (int e = 0; e < 16; e++) s += w_out[d * 16 + e] * fc_w[e * 32 + j];
        g_W2[i] = s;
    }
    if (i < 32) {
        float s = fc_b[i];
#pragma unroll
        for (int e = 0; e < 16; e++) s += b_out[e] * fc_w[e * 32 + i];
        g_b2[i] = s;
    }
}

__global__ void __launch_bounds__(128, 4)
face_kernel(const float* __restrict__ node, const int* __restrict__ fids,
            const float* __restrict__ w_in, const float* __restrict__ b_in,
            const float* __restrict__ fco_w, const float* __restrict__ fco_b,
            float* __restrict__ out, int F) {
    __shared__ __align__(16) float s_win[16 * 48];   // packed qkv weights [d][o]
    __shared__ __align__(16) float s_bin[48];
    __shared__ __align__(16) float s_W2[16 * 32];    // fused w_out@fc_w
    __shared__ __align__(16) float s_b2[32];
    __shared__ __align__(16) float s_fco[32 * 32];
    __shared__ __align__(16) float s_fcob[32];
    __shared__ __align__(16) float s_stage[4][8][132];  // [warp][slot][quad*16+chunk*4]

    int tid = threadIdx.x;
    int gt = blockIdx.x * 128 + tid;
    int faceR = gt >> 1;            // real face (may be >= F for tail lanes)
    int h = gt & 1;                 // head index (0 or 1)
    bool valid = faceR < F;
    int face = valid ? faceR : (F - 1);  // clamped for loads

    int lane = tid & 31;
    int wq = lane >> 2;             // quad index within warp (0..7)
    int ql = lane & 3;              // lane within quad

    // ---- gather FIRST: fids + 8 node LDGs in flight before weight fills ----
    int4 Im = *(const int4*)(fids + 4ll * face);
    int ox = __shfl_xor_sync(0xffffffffu, Im.x, 2);
    int oy = __shfl_xor_sync(0xffffffffu, Im.y, 2);
    int oz = __shfl_xor_sync(0xffffffffu, Im.z, 2);
    int ow = __shfl_xor_sync(0xffffffffu, Im.w, 2);
    bool isB = (lane & 2) != 0;
    int IAx = isB ? ox : Im.x, IAy = isB ? oy : Im.y;
    int IAz = isB ? oz : Im.z, IAw = isB ? ow : Im.w;
    int IBx = isB ? Im.x : ox, IBy = isB ? Im.y : oy;
    int IBz = isB ? Im.z : oz, IBw = isB ? Im.w : ow;
    long long co = 4 * ql;          // chunk offset in floats
    float4 r0 = *(const float4*)(node + 16ll * IAx + co);
    float4 r1 = *(const float4*)(node + 16ll * IAz + co);
    float4 r2 = *(const float4*)(node + 16ll * IBx + co);
    float4 r3 = *(const float4*)(node + 16ll * IBz + co);
    float4 r4 = *(const float4*)(node + 16ll * IAy + co);
    float4 r5 = *(const float4*)(node + 16ll * IAw + co);
    float4 r6 = *(const float4*)(node + 16ll * IBy + co);
    float4 r7 = *(const float4*)(node + 16ll * IBw + co);

    // ---- weight smem fills overlap the gather latency ----
    for (int i = tid; i < 768; i += 128) s_win[i] = w_in[i];
    if (tid < 48) s_bin[tid] = b_in[tid];
    for (int i = tid; i < 512; i += 128) s_W2[i] = g_W2[i];
    if (tid < 32) s_b2[tid] = g_b2[tid];
    for (int i = tid; i < 1024; i += 128) s_fco[i] = fco_w[i];
    if (tid < 32) s_fcob[tid] = fco_b[tid];

    // ---- stage-store + warp-local redistribution (no block barrier needed) ----
    float* st = &s_stage[tid >> 5][0][0];
    {
        int so = wq * 16 + ql * 4;
        *(float4*)(st + 0 * 132 + so) = r0;
        *(float4*)(st + 1 * 132 + so) = r1;
        *(float4*)(st + 2 * 132 + so) = r2;
        *(float4*)(st + 3 * 132 + so) = r3;
        *(float4*)(st + 4 * 132 + so) = r4;
        *(float4*)(st + 5 * 132 + so) = r5;
        *(float4*)(st + 6 * 132 + so) = r6;
        *(float4*)(st + 7 * 132 + so) = r7;
    }
    __syncwarp();
    float4 XA[4], XB[4];
    {
        const float* pa = st + ql * 132 + wq * 16;
        const float* pb = st + (ql + 4) * 132 + wq * 16;
#pragma unroll
        for (int cc = 0; cc < 4; cc++) {
            XA[cc] = *(const float4*)(pa + cc * 4);
            XB[cc] = *(const float4*)(pb + cc * 4);
        }
    }

    __syncthreads();   // weights ready before first use

    // Lane-local token order: 0 = own_a, 1 = own_b, 2 = partner_a, 3 = partner_b.

    // ---- phase 1a: q,k for all 4 tokens (own head), d-outer for weight reuse ----
    u64 q2[4][4], k2[4][4];
    {
        const u64* bq = (const u64*)(s_bin + 8 * h);
        const u64* bk = (const u64*)(s_bin + 16 + 8 * h);
#pragma unroll
        for (int t = 0; t < 4; t++)
#pragma unroll
            for (int j = 0; j < 4; j++) { q2[t][j] = bq[j]; k2[t][j] = bk[j]; }
    }
    {
        const float* wqp = s_win + 8 * h;
        const float* wkp = s_win + 16 + 8 * h;
#pragma unroll
        for (int d = 0; d < 16; d++) {
            ulonglong2 wq0 = *(const ulonglong2*)(wqp + d * 48);
            ulonglong2 wq1 = *(const ulonglong2*)(wqp + d * 48 + 4);
            ulonglong2 wk0 = *(const ulonglong2*)(wkp + d * 48);
            ulonglong2 wk1 = *(const ulonglong2*)(wkp + d * 48 + 4);
            float xa = getc(XA[d >> 2], d & 3);
            float xb = getc(XB[d >> 2], d & 3);
            float fa = __shfl_xor_sync(0xffffffffu, xa, 1);
            float fb = __shfl_xor_sync(0xffffffffu, xb, 1);
            u64 xt[4] = {pack2(xa, xa), pack2(xb, xb), pack2(fa, fa), pack2(fb, fb)};
#pragma unroll
            for (int t = 0; t < 4; t++) {
                q2[t][0] = fma2(xt[t], wq0.x, q2[t][0]);
                q2[t][1] = fma2(xt[t], wq0.y, q2[t][1]);
                q2[t][2] = fma2(xt[t], wq1.x, q2[t][2]);
                q2[t][3] = fma2(xt[t], wq1.y, q2[t][3]);
                k2[t][0] = fma2(xt[t], wk0.x, k2[t][0]);
                k2[t][1] = fma2(xt[t], wk0.y, k2[t][1]);
                k2[t][2] = fma2(xt[t], wk1.x, k2[t][2]);
                k2[t][3] = fma2(xt[t], wk1.y, k2[t][3]);
            }
        }
    }

    // ---- scores + softmax (own head, 4x4, lane-local token order) ----
    float att[4][4];
    const float RS = 0.35355339059327373f;  // 1/sqrt(8)
#pragma unroll
    for (int qi = 0; qi < 4; qi++) {
#pragma unroll
        for (int ki = 0; ki < 4; ki++) {
            u64 a = fma2(q2[qi][0], k2[ki][0], 0ull);
            a = fma2(q2[qi][1], k2[ki][1], a);
            a = fma2(q2[qi][2], k2[ki][2], a);
            a = fma2(q2[qi][3], k2[ki][3], a);
            float2 p = unpack2(a);
            att[qi][ki] = (p.x + p.y) * RS;
        }
        float m = fmaxf(fmaxf(att[qi][0], att[qi][1]), fmaxf(att[qi][2], att[qi][3]));
        float e0 = __expf(att[qi][0] - m);
        float e1 = __expf(att[qi][1] - m);
        float e2 = __expf(att[qi][2] - m);
        float e3 = __expf(att[qi][3] - m);
        float inv = 1.0f / (e0 + e1 + e2 + e3);
        att[qi][0] = e0 * inv; att[qi][1] = e1 * inv;
        att[qi][2] = e2 * inv; att[qi][3] = e3 * inv;
    }

    // ---- phase 1b: v for all 4 tokens (own head), d-outer ----
    u64 v2[4][4];
    {
        const u64* bv = (const u64*)(s_bin + 32 + 8 * h);
#pragma unroll
        for (int t = 0; t < 4; t++)
#pragma unroll
            for (int j = 0; j < 4; j++) v2[t][j] = bv[j];
    }
    {
        const float* wvp = s_win + 32 + 8 * h;
#pragma unroll
        for (int d = 0; d < 16; d++) {
            ulonglong2 wv0 = *(const ulonglong2*)(wvp + d * 48);
            ulonglong2 wv1 = *(const ulonglong2*)(wvp + d * 48 + 4);
            float xa = getc(XA[d >> 2], d & 3);
            float xb = getc(XB[d >> 2], d & 3);
            float fa = __shfl_xor_sync(0xffffffffu, xa, 1);
            float fb = __shfl_xor_sync(0xffffffffu, xb, 1);
            u64 xt[4] = {pack2(xa, xa), pack2(xb, xb), pack2(fa, fa), pack2(fb, fb)};
#pragma unroll
            for (int t = 0; t < 4; t++) {
                v2[t][0] = fma2(xt[t], wv0.x, v2[t][0]);
                v2[t][1] = fma2(xt[t], wv0.y, v2[t][1]);
                v2[t][2] = fma2(xt[t], wv1.x, v2[t][2]);
                v2[t][3] = fma2(xt[t], wv1.y, v2[t][3]);
            }
        }
    }

    // ---- o = attn @ v for all 4 local query tokens (own head half: 8 dims) ----
    u64 o2[4][4];
#pragma unroll
    for (int qi = 0; qi < 4; qi++) {
#pragma unroll
        for (int j = 0; j < 4; j++) o2[qi][j] = 0ull;
#pragma unroll
        for (int s = 0; s < 4; s++) {
            u64 a2 = pack2(att[qi][s], att[qi][s]);
#pragma unroll
            for (int j = 0; j < 4; j++) o2[qi][j] = fma2(a2, v2[s][j], o2[qi][j]);
        }
    }

    // ---- W2 col-split with PROGRESSIVE o-exchange ----
    u64 acc[4][8];
    {
        const u64* bb = (const u64*)(s_b2 + 16 * h);
#pragma unroll
        for (int t = 0; t < 4; t++)
#pragma unroll
            for (int j = 0; j < 8; j++) acc[t][j] = bb[j];
    }
    {
        const float* wbaseA = s_W2 + (8 * h) * 32 + 16 * h;
#pragma unroll
        for (int dd = 0; dd < 8; dd++) {
            const ulonglong2* wr = (const ulonglong2*)(wbaseA + dd * 32);
            ulonglong2 wa = wr[0], wb = wr[1], wc = wr[2], wd_ = wr[3];
#pragma unroll
            for (int t = 0; t < 4; t++) {
                float2 p = unpack2(o2[t][dd >> 1]);
                float ov = (dd & 1) ? p.y : p.x;
                u64 op = pack2(ov, ov);
                acc[t][0] = fma2(op, wa.x, acc[t][0]);
                acc[t][1] = fma2(op, wa.y, acc[t][1]);
                acc[t][2] = fma2(op, wb.x, acc[t][2]);
                acc[t][3] = fma2(op, wb.y, acc[t][3]);
                acc[t][4] = fma2(op, wc.x, acc[t][4]);
                acc[t][5] = fma2(op, wc.y, acc[t][5]);
                acc[t][6] = fma2(op, wd_.x, acc[t][6]);
                acc[t][7] = fma2(op, wd_.y, acc[t][7]);
            }
        }
    }
    u64 rcv[4][4];
#pragma unroll
    for (int t = 0; t < 4; t++)
#pragma unroll
        for (int j = 0; j < 4; j++)
            rcv[t][j] = __shfl_xor_sync(0xffffffffu, o2[t ^ 2][j], 1);
    {
        const float* wbaseB = s_W2 + (8 * (1 - h)) * 32 + 16 * h;
#pragma unroll
        for (int dd = 0; dd < 8; dd++) {
            const ulonglong2* wr = (const ulonglong2*)(wbaseB + dd * 32);
            ulonglong2 wa = wr[0], wb = wr[1], wc = wr[2], wd_ = wr[3];
#pragma unroll
            for (int t = 0; t < 4; t++) {
                float2 p = unpack2(rcv[t][dd >> 1]);
                float ov = (dd & 1) ? p.y : p.x;
                u64 op = pack2(ov, ov);
                acc[t][0] = fma2(op, wa.x, acc[t][0]);
                acc[t][1] = fma2(op, wa.y, acc[t][1]);
                acc[t][2] = fma2(op, wb.x, acc[t][2]);
                acc[t][3] = fma2(op, wb.y, acc[t][3]);
                acc[t][4] = fma2(op, wc.x, acc[t][4]);
                acc[t][5] = fma2(op, wc.y, acc[t][5]);
                acc[t][6] = fma2(op, wd_.x, acc[t][6]);
                acc[t][7] = fma2(op, wd_.y, acc[t][7]);
            }
        }
    }

    // ---- relu + mean over 4 tokens (thread-local) ----
    u64 pool[8];   // my 16 cols
#pragma unroll
    for (int j = 0; j < 8; j++) {
        float px = 0.f, py = 0.f;
#pragma unroll
        for (int t = 0; t < 4; t++) {
            float2 a = unpack2(acc[t][j]);
            px += fmaxf(a.x, 0.f);
            py += fmaxf(a.y, 0.f);
        }
        pool[j] = pack2(px * 0.25f, py * 0.25f);
    }

    // ---- butterfly: full 32 pooled for own face (xor1), then partner face (xor2) ----
    u64 pown[16];
#pragma unroll
    for (int j = 0; j < 8; j++) {
        u64 other = __shfl_xor_sync(0xffffffffu, pool[j], 1);
        pown[j]     = h ? other : pool[j];
        pown[8 + j] = h ? pool[j] : other;
    }
    u64 poth[16];
#pragma unroll
    for (int j = 0; j < 16; j++)
        poth[j] = __shfl_xor_sync(0xffffffffu, pown[j], 2);

    // ---- fco quad-split: col octet [8c, 8c+8), c = tid&3, for BOTH quad faces ----
    int c = tid & 3;
    u64 accA[4], accB[4];
    {
        const u64* fb = (const u64*)(s_fcob + 8 * c);
#pragma unroll
        for (int p = 0; p < 4; p++) { accA[p] = fb[p]; accB[p] = fb[p]; }
    }
    const float* fch = s_fco + 8 * c;
#pragma unroll
    for (int e = 0; e < 32; e++) {
        float2 ppA = unpack2(pown[e >> 1]);
        float2 ppB = unpack2(poth[e >> 1]);
        float peA = (e & 1) ? ppA.y : ppA.x;
        float peB = (e & 1) ? ppB.y : ppB.x;
        u64 pA2 = pack2(peA, peA);
        u64 pB2 = pack2(peB, peB);
        const ulonglong2* fr = (const ulonglong2*)(fch + e * 32);
        ulonglong2 wa = fr[0], wb = fr[1];
        accA[0] = fma2(pA2, wa.x, accA[0]);
        accA[1] = fma2(pA2, wa.y, accA[1]);
        accA[2] = fma2(pA2, wb.x, accA[2]);
        accA[3] = fma2(pA2, wb.y, accA[3]);
        accB[0] = fma2(pB2, wa.x, accB[0]);
        accB[1] = fma2(pB2, wa.y, accB[1]);
        accB[2] = fma2(pB2, wb.x, accB[2]);
        accB[3] = fma2(pB2, wb.y, accB[3]);
    }

    // ---- stores: face A = my real face; face B = quad partner's face (^1) ----
    int faceB = faceR ^ 1;
    if (valid) {
        float* opA = out + 32ll * faceR + 8 * c;
        float2 a0 = unpack2(accA[0]), a1 = unpack2(accA[1]);
        float2 a2 = unpack2(accA[2]), a3 = unpack2(accA[3]);
        ((float4*)opA)[0] = make_float4(a0.x, a0.y, a1.x, a1.y);
        ((float4*)opA)[1] = make_float4(a2.x, a2.y, a3.x, a3.y);
    }
    if (faceB < F) {
        float* opB = out + 32ll * faceB + 8 * c;
        float2 b0 = unpack2(accB[0]), b1 = unpack2(accB[1]);
        float2 b2 = unpack2(accB[2]), b3 = unpack2(accB[3]);
        ((float4*)opB)[0] = make_float4(b0.x, b0.y, b1.x, b1.y);
        ((float4*)opB)[1] = make_float4(b2.x, b2.y, b3.x, b3.y);
    }
}

extern "C" void kernel_launch(void* const* d_in, const int* in_sizes, int n_in,
                              void* d_out, int out_size) {
    const float* node  = (const float*)d_in[0];
    const int*   fids  = (const int*)d_in[1];
    const float* w_in  = (const float*)d_in[2];
    const float* b_in  = (const float*)d_in[3];
    const float* w_out = (const float*)d_in[4];
    const float* b_out = (const float*)d_in[5];
    const float* fc_w  = (const float*)d_in[6];
    const float* fc_b  = (const float*)d_in[7];
    const float* fco_w = (const float*)d_in[8];
    const float* fco_b = (const float*)d_in[9];

    int F = in_sizes[1] / 4;

    prep_kernel<<<1, 512>>>(w_out, b_out, fc_w, fc_b);

    long long threads = 2ll * F;
    int blocks = (int)((threads + 127) / 128);
    face_kernel<<<blocks, 128>>>(node, fids, w_in, b_in, fco_w, fco_b, (float*)d_out, F);
}